// round 12
// baseline (speedup 1.0000x reference)
#include <cuda_runtime.h>
#include <cuda_fp16.h>
#include <math.h>
#include <string.h>

#define H_    512
#define W_    1408
#define HW    (H_ * W_)        // 720896 = 704 * 1024
#define NPTS  640000
#define NCAM  6
#define NCH   17

// Scratch (allocation-free rule: __device__ globals).
// Ping-pong image buffers: 16ch fp16 plane (32B/px, 23MB) + planar ch16 (1.4MB).
// buf0 owned by even-camera chain, buf1 by odd chain; loss(c) re-zeroes its
// buffer before splat(c+2) reuses it (same-stream ordering).
__device__ __align__(256) __half g16[2][(size_t)HW * 16];
__device__ __align__(256) __half g1[2][(size_t)HW + 8];
__device__ float g_num[NCAM];
__device__ float g_den[NCAM];

// Packed per-point inputs, rebuilt by pack_kernel every launch.
__device__ __align__(256) uint4  g_pf[(size_t)NPTS * 2];  // ch0..15 as 16 fp16 (32B/pt)
__device__ __align__(256) float2 g_aux[NPTS];             // (ch16 fp32, opacity fp32)
__device__ __align__(256) float4 g_xyzw[NPTS];            // xyz + pad

__device__ __forceinline__ unsigned h2_bits(__half2 h) {
    unsigned u;
    memcpy(&u, &h, 4);
    return u;
}

__device__ __forceinline__ void red_add_v4_h2(__half* addr, unsigned a, unsigned b,
                                              unsigned c, unsigned d) {
    asm volatile("red.global.add.noftz.v4.f16x2 [%0], {%1, %2, %3, %4};"
                 :: "l"(addr), "r"(a), "r"(b), "r"(c), "r"(d)
                 : "memory");
}
__device__ __forceinline__ void red_add_h(__half* addr, __half v) {
    unsigned short s;
    memcpy(&s, &v, 2);
    asm volatile("red.global.add.noftz.f16 [%0], %1;"
                 :: "l"(addr), "h"(s)
                 : "memory");
}

// One-shot input pack: feats->fp16x16 + (ch16,opac) float2 + xyz float4.
__global__ __launch_bounds__(256)
void pack_kernel(const float* __restrict__ feats,
                 const float* __restrict__ density,
                 const float* __restrict__ xyz)
{
    int p = blockIdx.x * 256 + threadIdx.x;
    if (p >= NPTS) return;

    float f[NCH];
#pragma unroll
    for (int ch = 0; ch < NCH; ch++) f[ch] = __ldcs(feats + (size_t)p * NCH + ch);

    __half2 h[8];
#pragma unroll
    for (int i = 0; i < 8; i++) h[i] = __floats2half2_rn(f[2 * i], f[2 * i + 1]);

    uint4 q0, q1;
    q0.x = h2_bits(h[0]); q0.y = h2_bits(h[1]); q0.z = h2_bits(h[2]); q0.w = h2_bits(h[3]);
    q1.x = h2_bits(h[4]); q1.y = h2_bits(h[5]); q1.z = h2_bits(h[6]); q1.w = h2_bits(h[7]);
    g_pf[(size_t)p * 2 + 0] = q0;
    g_pf[(size_t)p * 2 + 1] = q1;

    g_aux[p]  = make_float2(f[16], __ldcs(density + p));
    g_xyzw[p] = make_float4(__ldcs(xyz + 3 * p + 0),
                            __ldcs(xyz + 3 * p + 1),
                            __ldcs(xyz + 3 * p + 2), 0.0f);
}

// Warp-cooperative splat: each warp handles 32 points, one per step.
// Lanes 0..17: the 18 x 16B chunks of the 3-pixel x 3-row 16-ch footprint
//   (one v4.f16x2 RED -> ~9 coherent sectors instead of 32 scattered).
// Lanes 18..26: the 9 ch16 scalar taps. Lanes 27..31 idle.
// Out-of-bounds taps: clamped address + w=0 (+0.0h add, numerically exact).
__global__ __launch_bounds__(256)
void splat_kernel(int cam, int buf,
                  const float* __restrict__ viewmats,
                  const float* __restrict__ Ks)
{
    int lane = threadIdx.x & 31;
    int p0 = blockIdx.x * 256 + (threadIdx.x & ~31);   // warp's first point

    const float* V = viewmats + cam * 16;
    const float* K = Ks + cam * 9;
    float V0 = V[0], V1 = V[1], V2 = V[2],  V3  = V[3];
    float V4 = V[4], V5 = V[5], V6 = V[6],  V7  = V[7];
    float V8 = V[8], V9 = V[9], V10 = V[10], V11 = V[11];
    float fx = K[0], cx = K[2], fy = K[4], cy = K[5];

    // lane tap role (constant per lane)
    bool isMain = lane < 18;
    bool isC16  = (lane >= 18) && (lane < 27);
    int mrow, mdx, grp;
    if (isMain) { mrow = lane / 6; int k = lane % 6; mdx = k >> 1; grp = k & 1; }
    else if (isC16) { int t = lane - 18; mrow = t / 3; mdx = t % 3; grp = 0; }
    else { mrow = 0; mdx = 0; grp = 0; }

    __half* img16 = g16[buf];
    __half* img1  = g1[buf];
    const float s2 = 0.16f;

#pragma unroll 2
    for (int s = 0; s < 32; s++) {
        int p = p0 + s;
        float4 P = g_xyzw[p];                       // uniform address -> broadcast

        float px = fmaf(V0, P.x, fmaf(V1, P.y, fmaf(V2,  P.z, V3)));
        float py = fmaf(V4, P.x, fmaf(V5, P.y, fmaf(V6,  P.z, V7)));
        float pz = fmaf(V8, P.x, fmaf(V9, P.y, fmaf(V10, P.z, V11)));

        if (!(pz > 0.1f)) continue;                 // warp-uniform

        float z  = fmaxf(pz, 0.001f);
        float rz = __fdividef(1.0f, z);
        float u  = fmaf(fx * px, rz, cx);
        float v  = fmaf(fy * py, rz, cy);

        float j00 = fx * rz, j11 = fy * rz;
        float j02 = -(fx * px * rz) * rz;
        float j12 = -(fy * py * rz) * rz;

        float a  = s2 * (j00 * j00 + j02 * j02) + 0.3f;
        float b  = s2 * (j02 * j12);
        float cq = s2 * (j11 * j11 + j12 * j12) + 0.3f;
        float det  = a * cq - b * b;
        float rdet = __fdividef(1.0f, det);
        float ca = cq * rdet, cb = -b * rdet, cc = a * rdet;

        float ru = rintf(u);
        float rv = rintf(v);
        if (ru < -1.0f || ru > (float)W_ || rv < -1.0f || rv > (float)H_) continue;  // uniform

        float2 aux = g_aux[p];                      // (ch16, opacity), uniform addr

        // my tap
        float pyy = rv + (float)(mrow - 1);
        float pxx = ru + (float)(mdx  - 1);
        bool valid = (lane < 27) && (pxx >= 0.0f) && (pxx < (float)W_)
                                 && (pyy >= 0.0f) && (pyy < (float)H_);
        float ddx = pxx - u;
        float ddy = pyy - v;
        float e = -0.5f * (ca * ddx * ddx + 2.0f * cb * ddx * ddy + cc * ddy * ddy);
        float w = valid ? aux.y * __expf(e) : 0.0f;

        int pyi = min(max((int)pyy, 0), H_ - 1);
        int pxi = min(max((int)pxx, 0), W_ - 1);
        int pix = pyi * W_ + pxi;

        if (isMain) {
            uint4 q = g_pf[(size_t)p * 2 + grp];    // 2 distinct addrs warp-wide
            __half2 wh = __float2half2_rn(w);
            __half2 f0, f1, f2, f3;
            memcpy(&f0, &q.x, 4); memcpy(&f1, &q.y, 4);
            memcpy(&f2, &q.z, 4); memcpy(&f3, &q.w, 4);
            red_add_v4_h2(img16 + (size_t)pix * 16 + grp * 8,
                          h2_bits(__hmul2(wh, f0)), h2_bits(__hmul2(wh, f1)),
                          h2_bits(__hmul2(wh, f2)), h2_bits(__hmul2(wh, f3)));
        } else if (isC16) {
            red_add_h(img1 + pix, __float2half_rn(w * aux.x));
        }
    }
}

// Loss: 352 blocks x 256 threads x 8 pixels (MLP-heavy).
__global__ __launch_bounds__(256)
void loss_kernel(int cam, int buf, const int* __restrict__ gt, const float* __restrict__ cw)
{
    float nwl = 0.0f, wv = 0.0f;
    __half* img16 = g16[buf];
    __half* img1  = g1[buf];

#pragma unroll
    for (int j = 0; j < 8; j++) {
        int pix = blockIdx.x * 2048 + j * 256 + threadIdx.x;
        __half* bp = img16 + (size_t)pix * 16;

        uint4 q0 = ((const uint4*)bp)[0];   // halves 0..7
        uint4 q1 = ((const uint4*)bp)[1];   // halves 8..15
        __half h16 = img1[pix];

        float l[NCH];
        {
            float2 t;
            t = __half22float2(*(__half2*)&q0.x); l[0] = t.x;  l[1] = t.y;
            t = __half22float2(*(__half2*)&q0.y); l[2] = t.x;  l[3] = t.y;
            t = __half22float2(*(__half2*)&q0.z); l[4] = t.x;  l[5] = t.y;
            t = __half22float2(*(__half2*)&q0.w); l[6] = t.x;  l[7] = t.y;
            t = __half22float2(*(__half2*)&q1.x); l[8] = t.x;  l[9] = t.y;
            t = __half22float2(*(__half2*)&q1.y); l[10] = t.x; l[11] = t.y;
            t = __half22float2(*(__half2*)&q1.z); l[12] = t.x; l[13] = t.y;
            t = __half22float2(*(__half2*)&q1.w); l[14] = t.x; l[15] = t.y;
            l[16] = __half2float(h16);
        }

        float m = l[0];
#pragma unroll
        for (int ch = 1; ch < NCH; ch++) m = fmaxf(m, l[ch]);
        float s = 0.0f;
#pragma unroll
        for (int ch = 0; ch < NCH; ch++) s += __expf(l[ch] - m);
        float lse = m + __logf(s);

        int g = __ldcs(gt + (size_t)cam * HW + pix);  // in [0,17)
        float lg = (g < 16) ? __half2float(bp[g]) : l[16];
        float w = (g != 0) ? cw[g] : 0.0f;

        nwl += w * (lse - lg);
        wv  += w;

        // restore invariant: zero the image before this buffer's next splat
        uint4 z4 = make_uint4(0u, 0u, 0u, 0u);
        ((uint4*)bp)[0] = z4;
        ((uint4*)bp)[1] = z4;
        img1[pix] = __ushort_as_half((unsigned short)0);
    }

    // block reduction
#pragma unroll
    for (int o = 16; o > 0; o >>= 1) {
        nwl += __shfl_down_sync(0xffffffffu, nwl, o);
        wv  += __shfl_down_sync(0xffffffffu, wv,  o);
    }
    __shared__ float sh[16];
    int lane = threadIdx.x & 31;
    int wid  = threadIdx.x >> 5;
    if (lane == 0) { sh[wid] = nwl; sh[8 + wid] = wv; }
    __syncthreads();
    if (threadIdx.x == 0) {
        float an = 0.0f, ad = 0.0f;
#pragma unroll
        for (int i = 0; i < 8; i++) { an += sh[i]; ad += sh[8 + i]; }
        atomicAdd(&g_num[cam], an);
        atomicAdd(&g_den[cam], ad);
    }
}

__global__ void finalize_kernel(float* out)
{
    if (threadIdx.x == 0 && blockIdx.x == 0) {
        float L = 0.0f;
#pragma unroll
        for (int cam = 0; cam < NCAM; cam++) {
            L += g_num[cam] / fmaxf(g_den[cam], 1e-8f);
            g_num[cam] = 0.0f;   // reset accumulators for next replay
            g_den[cam] = 0.0f;
        }
        out[0] = L / (float)NCAM;
    }
}

// One-time side-stream + fork/join events. Created on the (uncaptured)
// correctness call; captured calls only record/wait — graph-legal fork-join.
static cudaStream_t get_side_stream() {
    static cudaStream_t s = [] {
        cudaStream_t t;
        cudaStreamCreateWithFlags(&t, cudaStreamNonBlocking);
        return t;
    }();
    return s;
}
static cudaEvent_t get_event(int which) {
    static cudaEvent_t e[2] = { [] {
        cudaEvent_t t;
        cudaEventCreateWithFlags(&t, cudaEventDisableTiming);
        return t;
    }(), [] {
        cudaEvent_t t;
        cudaEventCreateWithFlags(&t, cudaEventDisableTiming);
        return t;
    }() };
    return e[which];
}

extern "C" void kernel_launch(void* const* d_in, const int* in_sizes, int n_in,
                              void* d_out, int out_size)
{
    const float* voxel_feats = (const float*)d_in[0];
    const float* density     = (const float*)d_in[1];
    const float* viewmats    = (const float*)d_in[2];
    const float* Ks          = (const float*)d_in[3];
    const int*   gt_sem      = (const int*)d_in[4];
    const float* pc_xyz      = (const float*)d_in[5];
    const float* cls_w       = (const float*)d_in[6];

    cudaStream_t s1 = get_side_stream();
    cudaEvent_t eFork = get_event(0);
    cudaEvent_t eJoin = get_event(1);

    // pack inputs once (ordered before both chains)
    pack_kernel<<<(NPTS + 255) / 256, 256>>>(voxel_feats, density, pc_xyz);

    // fork: odd-camera chain runs on s1, concurrent with the even chain
    cudaEventRecord(eFork, 0);
    cudaStreamWaitEvent(s1, eFork, 0);

    for (int cam = 0; cam < NCAM; cam++) {
        int buf = cam & 1;
        cudaStream_t st = (cam & 1) ? s1 : 0;
        splat_kernel<<<(NPTS + 255) / 256, 256, 0, st>>>(cam, buf, viewmats, Ks);
        loss_kernel<<<HW / 2048, 256, 0, st>>>(cam, buf, gt_sem, cls_w);
    }

    // join: finalize after both chains complete
    cudaEventRecord(eJoin, s1);
    cudaStreamWaitEvent(0, eJoin, 0);
    finalize_kernel<<<1, 32>>>((float*)d_out);
}

// round 13
// speedup vs baseline: 3.0926x; 3.0926x over previous
#include <cuda_runtime.h>
#include <cuda_fp16.h>
#include <math.h>
#include <string.h>

#define H_    512
#define W_    1408
#define HW    (H_ * W_)        // 720896 = 704 * 1024
#define NPTS  640000
#define NCAM  6
#define NCH   17

// Scratch (allocation-free rule: __device__ globals).
// Ping-pong image buffers: 16ch fp16 plane (32B/px, 23MB) + planar ch16 (1.4MB).
// buf0 owned by even-camera chain, buf1 by odd chain; loss(c) re-zeroes its
// buffer before splat(c+2) reuses it (same-stream ordering; the split final
// loss is ordered after splat5 on both streams via event).
__device__ __align__(256) __half g16[2][(size_t)HW * 16];
__device__ __align__(256) __half g1[2][(size_t)HW + 8];
__device__ float g_num[NCAM];
__device__ float g_den[NCAM];

__device__ __forceinline__ unsigned h2_bits(__half2 h) {
    unsigned u;
    memcpy(&u, &h, 4);
    return u;
}

__device__ __forceinline__ void red_add_v4_h2(__half* addr, unsigned a, unsigned b,
                                              unsigned c, unsigned d) {
    asm volatile("red.global.add.noftz.v4.f16x2 [%0], {%1, %2, %3, %4};"
                 :: "l"(addr), "r"(a), "r"(b), "r"(c), "r"(d)
                 : "memory");
}
__device__ __forceinline__ void red_add_h2(__half* addr, __half2 v) {
    asm volatile("red.global.add.noftz.f16x2 [%0], %1;"
                 :: "l"(addr), "r"(h2_bits(v))
                 : "memory");
}
__device__ __forceinline__ void red_add_h(__half* addr, __half v) {
    unsigned short s;
    memcpy(&s, &v, 2);
    asm volatile("red.global.add.noftz.f16 [%0], %1;"
                 :: "l"(addr), "h"(s)
                 : "memory");
}

__global__ __launch_bounds__(256)
void splat_kernel(int cam, int buf,
                  const float* __restrict__ feats,
                  const float* __restrict__ density,
                  const float* __restrict__ viewmats,
                  const float* __restrict__ Ks,
                  const float* __restrict__ xyz)
{
    int p = blockIdx.x * 256 + threadIdx.x;
    if (p >= NPTS) return;

    float X = __ldcs(xyz + 3 * p + 0);
    float Y = __ldcs(xyz + 3 * p + 1);
    float Z = __ldcs(xyz + 3 * p + 2);

    const float* V = viewmats + cam * 16;
    const float* K = Ks + cam * 9;

    float px = V[0] * X + V[1] * Y + V[2]  * Z + V[3];
    float py = V[4] * X + V[5] * Y + V[6]  * Z + V[7];
    float pz = V[8] * X + V[9] * Y + V[10] * Z + V[11];

    // reference: valid requires p.z > 0.1 (else all 9 taps contribute 0)
    if (!(pz > 0.1f)) return;

    float z  = fmaxf(pz, 0.001f);
    float fx = K[0], cx = K[2], fy = K[4], cy = K[5];

    float u = fx * px / z + cx;
    float v = fy * py / z + cy;

    const float s2 = 0.4f * 0.4f;
    float j00 = fx / z;
    float j11 = fy / z;
    float j02 = -fx * px / (z * z);
    float j12 = -fy * py / (z * z);

    float a = s2 * (j00 * j00 + j02 * j02) + 0.3f;
    float b = s2 * (j02 * j12);
    float c = s2 * (j11 * j11 + j12 * j12) + 0.3f;
    float det = a * c - b * b;
    float ca =  c / det;
    float cb = -b / det;
    float cc =  a / det;

    float ru = rintf(u);   // matches jnp.round (half-to-even)
    float rv = rintf(v);

    // quick full-footprint reject (all 9 taps out of image)
    if (ru < -1.0f || ru > (float)W_ || rv < -1.0f || rv > (float)H_) return;

    float opac = __ldcs(density + p);

    // Pack the 17-ch feature vector into half2 registers (pad with 0).
    __half2 fh[8];
    __half  f16h;
    {
        float f[NCH];
#pragma unroll
        for (int ch = 0; ch < NCH; ch++) f[ch] = __ldcs(feats + (size_t)p * NCH + ch);
#pragma unroll
        for (int i = 0; i < 8; i++) fh[i] = __floats2half2_rn(f[2 * i], f[2 * i + 1]);
        f16h = __float2half_rn(f[16]);
    }

    __half* img16 = g16[buf];
    __half* img1  = g1[buf];

    int   iu      = (int)ru;
    bool  u_inner = (ru >= 1.0f) && (ru <= (float)(W_ - 2));  // all 3 dx taps in-bounds

#pragma unroll
    for (int r = 0; r < 3; r++) {
        float pyy = rv + (float)(r - 1);
        if (pyy < 0.0f || pyy >= (float)H_) continue;
        float ddy = pyy - v;
        int   rowbase = (int)pyy * W_ + iu - 1;   // pixel index of dx=-1 tap

        if (u_inner) {
            __half c16[3];
#pragma unroll
            for (int t = 0; t < 3; t++) {
                float ddx = (ru + (float)(t - 1)) - u;
                float e = -0.5f * (ca * ddx * ddx + 2.0f * cb * ddx * ddy + cc * ddy * ddy);
                float w = opac * __expf(e);
                __half2 wh = __float2half2_rn(w);

                __half* bp = img16 + (size_t)(rowbase + t) * 16;
                red_add_v4_h2(bp + 0, h2_bits(__hmul2(wh, fh[0])), h2_bits(__hmul2(wh, fh[1])),
                                      h2_bits(__hmul2(wh, fh[2])), h2_bits(__hmul2(wh, fh[3])));
                red_add_v4_h2(bp + 8, h2_bits(__hmul2(wh, fh[4])), h2_bits(__hmul2(wh, fh[5])),
                                      h2_bits(__hmul2(wh, fh[6])), h2_bits(__hmul2(wh, fh[7])));
                c16[t] = __hmul(__low2half(wh), f16h);
            }
            // merged ch16: 3 contiguous halves -> two 4B-aligned f16x2 REDs (+0 padding)
            const __half hz = __ushort_as_half((unsigned short)0);
            int  e2  = rowbase & ~1;
            bool odd = (rowbase & 1) != 0;
            __half2 h2a = odd ? __halves2half2(hz, c16[0]) : __halves2half2(c16[0], c16[1]);
            __half2 h2b = odd ? __halves2half2(c16[1], c16[2]) : __halves2half2(c16[2], hz);
            red_add_h2(img1 + e2,     h2a);
            red_add_h2(img1 + e2 + 2, h2b);
        } else {
            // border fallback: per-tap guarded (matches reference exactly)
#pragma unroll
            for (int t = 0; t < 3; t++) {
                float pxx = ru + (float)(t - 1);
                if (pxx < 0.0f || pxx >= (float)W_) continue;
                float ddx = pxx - u;
                float e = -0.5f * (ca * ddx * ddx + 2.0f * cb * ddx * ddy + cc * ddy * ddy);
                float w = opac * __expf(e);
                __half2 wh = __float2half2_rn(w);
                int pix = rowbase + t;
                __half* bp = img16 + (size_t)pix * 16;
                red_add_v4_h2(bp + 0, h2_bits(__hmul2(wh, fh[0])), h2_bits(__hmul2(wh, fh[1])),
                                      h2_bits(__hmul2(wh, fh[2])), h2_bits(__hmul2(wh, fh[3])));
                red_add_v4_h2(bp + 8, h2_bits(__hmul2(wh, fh[4])), h2_bits(__hmul2(wh, fh[5])),
                                      h2_bits(__hmul2(wh, fh[6])), h2_bits(__hmul2(wh, fh[7])));
                red_add_h(img1 + pix, __hmul(__low2half(wh), f16h));
            }
        }
    }
}

// Loss: blocks of 256 threads x 8 pixels; block_off allows splitting the grid
// across two streams for the final camera (tail reduction).
__global__ __launch_bounds__(256)
void loss_kernel(int cam, int buf, int block_off,
                 const int* __restrict__ gt, const float* __restrict__ cw)
{
    float nwl = 0.0f, wv = 0.0f;
    __half* img16 = g16[buf];
    __half* img1  = g1[buf];

#pragma unroll
    for (int j = 0; j < 8; j++) {
        int pix = (blockIdx.x + block_off) * 2048 + j * 256 + threadIdx.x;
        __half* bp = img16 + (size_t)pix * 16;

        uint4 q0 = ((const uint4*)bp)[0];   // halves 0..7
        uint4 q1 = ((const uint4*)bp)[1];   // halves 8..15
        __half h16 = img1[pix];

        float l[NCH];
        {
            float2 t;
            t = __half22float2(*(__half2*)&q0.x); l[0] = t.x;  l[1] = t.y;
            t = __half22float2(*(__half2*)&q0.y); l[2] = t.x;  l[3] = t.y;
            t = __half22float2(*(__half2*)&q0.z); l[4] = t.x;  l[5] = t.y;
            t = __half22float2(*(__half2*)&q0.w); l[6] = t.x;  l[7] = t.y;
            t = __half22float2(*(__half2*)&q1.x); l[8] = t.x;  l[9] = t.y;
            t = __half22float2(*(__half2*)&q1.y); l[10] = t.x; l[11] = t.y;
            t = __half22float2(*(__half2*)&q1.z); l[12] = t.x; l[13] = t.y;
            t = __half22float2(*(__half2*)&q1.w); l[14] = t.x; l[15] = t.y;
            l[16] = __half2float(h16);
        }

        float m = l[0];
#pragma unroll
        for (int ch = 1; ch < NCH; ch++) m = fmaxf(m, l[ch]);
        float s = 0.0f;
#pragma unroll
        for (int ch = 0; ch < NCH; ch++) s += __expf(l[ch] - m);
        float lse = m + __logf(s);

        int g = __ldcs(gt + (size_t)cam * HW + pix);  // in [0,17)
        float lg = (g < 16) ? __half2float(bp[g]) : l[16];
        float w = (g != 0) ? cw[g] : 0.0f;

        nwl += w * (lse - lg);
        wv  += w;

        // restore invariant: zero the image before this buffer's next splat
        uint4 z4 = make_uint4(0u, 0u, 0u, 0u);
        ((uint4*)bp)[0] = z4;
        ((uint4*)bp)[1] = z4;
        img1[pix] = __ushort_as_half((unsigned short)0);
    }

    // block reduction
#pragma unroll
    for (int o = 16; o > 0; o >>= 1) {
        nwl += __shfl_down_sync(0xffffffffu, nwl, o);
        wv  += __shfl_down_sync(0xffffffffu, wv,  o);
    }
    __shared__ float sh[16];
    int lane = threadIdx.x & 31;
    int wid  = threadIdx.x >> 5;
    if (lane == 0) { sh[wid] = nwl; sh[8 + wid] = wv; }
    __syncthreads();
    if (threadIdx.x == 0) {
        float an = 0.0f, ad = 0.0f;
#pragma unroll
        for (int i = 0; i < 8; i++) { an += sh[i]; ad += sh[8 + i]; }
        atomicAdd(&g_num[cam], an);
        atomicAdd(&g_den[cam], ad);
    }
}

__global__ void finalize_kernel(float* out)
{
    if (threadIdx.x == 0 && blockIdx.x == 0) {
        float L = 0.0f;
#pragma unroll
        for (int cam = 0; cam < NCAM; cam++) {
            L += g_num[cam] / fmaxf(g_den[cam], 1e-8f);
            g_num[cam] = 0.0f;   // reset accumulators for next replay
            g_den[cam] = 0.0f;
        }
        out[0] = L / (float)NCAM;
    }
}

// One-time side-stream + fork/join events. Created on the (uncaptured)
// correctness call; captured calls only record/wait — graph-legal fork-join.
static cudaStream_t get_side_stream() {
    static cudaStream_t s = [] {
        cudaStream_t t;
        cudaStreamCreateWithFlags(&t, cudaStreamNonBlocking);
        return t;
    }();
    return s;
}
static cudaEvent_t get_event(int which) {
    static cudaEvent_t e[3] = { [] {
        cudaEvent_t t;
        cudaEventCreateWithFlags(&t, cudaEventDisableTiming);
        return t;
    }(), [] {
        cudaEvent_t t;
        cudaEventCreateWithFlags(&t, cudaEventDisableTiming);
        return t;
    }(), [] {
        cudaEvent_t t;
        cudaEventCreateWithFlags(&t, cudaEventDisableTiming);
        return t;
    }() };
    return e[which];
}

extern "C" void kernel_launch(void* const* d_in, const int* in_sizes, int n_in,
                              void* d_out, int out_size)
{
    const float* voxel_feats = (const float*)d_in[0];
    const float* density     = (const float*)d_in[1];
    const float* viewmats    = (const float*)d_in[2];
    const float* Ks          = (const float*)d_in[3];
    const int*   gt_sem      = (const int*)d_in[4];
    const float* pc_xyz      = (const float*)d_in[5];
    const float* cls_w       = (const float*)d_in[6];

    cudaStream_t s1 = get_side_stream();
    cudaEvent_t eFork   = get_event(0);
    cudaEvent_t eJoin   = get_event(1);
    cudaEvent_t eSplat5 = get_event(2);

    const int NBLK = HW / 2048;   // 352 loss blocks total

    // fork: odd-camera chain runs on s1, concurrent with the even chain
    cudaEventRecord(eFork, 0);
    cudaStreamWaitEvent(s1, eFork, 0);

    for (int cam = 0; cam < NCAM; cam++) {
        int buf = cam & 1;
        cudaStream_t st = (cam & 1) ? s1 : 0;
        splat_kernel<<<(NPTS + 255) / 256, 256, 0, st>>>(cam, buf, voxel_feats, density,
                                                         viewmats, Ks, pc_xyz);
        if (cam < NCAM - 1) {
            loss_kernel<<<NBLK, 256, 0, st>>>(cam, buf, 0, gt_sem, cls_w);
        } else {
            // final camera: split its loss across both streams to halve the tail
            cudaEventRecord(eSplat5, st);            // st == s1 (cam 5 odd)
            cudaStreamWaitEvent(0, eSplat5, 0);      // s0 idle by now
            loss_kernel<<<NBLK / 2, 256, 0, st>>>(cam, buf, 0, gt_sem, cls_w);
            loss_kernel<<<NBLK - NBLK / 2, 256, 0, 0>>>(cam, buf, NBLK / 2, gt_sem, cls_w);
        }
    }

    // join: finalize after both chains complete
    cudaEventRecord(eJoin, s1);
    cudaStreamWaitEvent(0, eJoin, 0);
    finalize_kernel<<<1, 32>>>((float*)d_out);
}

// round 14
// speedup vs baseline: 3.1635x; 1.0229x over previous
#include <cuda_runtime.h>
#include <cuda_fp16.h>
#include <math.h>
#include <string.h>

#define H_    512
#define W_    1408
#define HW    (H_ * W_)        // 720896 = 704 * 1024
#define NPTS  640000
#define NCAM  6
#define NCH   17
#define NBUF  3

// Scratch (allocation-free rule: __device__ globals).
// THREE ping-pong image buffers: 16ch fp16 plane (32B/px, 23MB each) + planar
// ch16 (1.4MB each) = ~73MB total, L2-resident. Chain k (stream k) owns buffer
// k and runs cams {k, k+3}; loss(k) re-zeroes its buffer before splat(k+3)
// reuses it (same-stream ordering). All buffers zero at entry of every launch.
__device__ __align__(256) __half g16[NBUF][(size_t)HW * 16];
__device__ __align__(256) __half g1[NBUF][(size_t)HW + 8];
__device__ float g_num[NCAM];
__device__ float g_den[NCAM];

__device__ __forceinline__ unsigned h2_bits(__half2 h) {
    unsigned u;
    memcpy(&u, &h, 4);
    return u;
}

__device__ __forceinline__ void red_add_v4_h2(__half* addr, unsigned a, unsigned b,
                                              unsigned c, unsigned d) {
    asm volatile("red.global.add.noftz.v4.f16x2 [%0], {%1, %2, %3, %4};"
                 :: "l"(addr), "r"(a), "r"(b), "r"(c), "r"(d)
                 : "memory");
}
__device__ __forceinline__ void red_add_h2(__half* addr, __half2 v) {
    asm volatile("red.global.add.noftz.f16x2 [%0], %1;"
                 :: "l"(addr), "r"(h2_bits(v))
                 : "memory");
}
__device__ __forceinline__ void red_add_h(__half* addr, __half v) {
    unsigned short s;
    memcpy(&s, &v, 2);
    asm volatile("red.global.add.noftz.f16 [%0], %1;"
                 :: "l"(addr), "h"(s)
                 : "memory");
}

__global__ __launch_bounds__(256)
void splat_kernel(int cam, int buf,
                  const float* __restrict__ feats,
                  const float* __restrict__ density,
                  const float* __restrict__ viewmats,
                  const float* __restrict__ Ks,
                  const float* __restrict__ xyz)
{
    int p = blockIdx.x * 256 + threadIdx.x;
    if (p >= NPTS) return;

    float X = __ldcs(xyz + 3 * p + 0);
    float Y = __ldcs(xyz + 3 * p + 1);
    float Z = __ldcs(xyz + 3 * p + 2);

    const float* V = viewmats + cam * 16;
    const float* K = Ks + cam * 9;

    float px = V[0] * X + V[1] * Y + V[2]  * Z + V[3];
    float py = V[4] * X + V[5] * Y + V[6]  * Z + V[7];
    float pz = V[8] * X + V[9] * Y + V[10] * Z + V[11];

    // reference: valid requires p.z > 0.1 (else all 9 taps contribute 0)
    if (!(pz > 0.1f)) return;

    float z  = fmaxf(pz, 0.001f);
    float fx = K[0], cx = K[2], fy = K[4], cy = K[5];

    float u = fx * px / z + cx;
    float v = fy * py / z + cy;

    const float s2 = 0.4f * 0.4f;
    float j00 = fx / z;
    float j11 = fy / z;
    float j02 = -fx * px / (z * z);
    float j12 = -fy * py / (z * z);

    float a = s2 * (j00 * j00 + j02 * j02) + 0.3f;
    float b = s2 * (j02 * j12);
    float c = s2 * (j11 * j11 + j12 * j12) + 0.3f;
    float det = a * c - b * b;
    float ca =  c / det;
    float cb = -b / det;
    float cc =  a / det;

    float ru = rintf(u);   // matches jnp.round (half-to-even)
    float rv = rintf(v);

    // quick full-footprint reject (all 9 taps out of image)
    if (ru < -1.0f || ru > (float)W_ || rv < -1.0f || rv > (float)H_) return;

    float opac = __ldcs(density + p);

    // Pack the 17-ch feature vector into half2 registers (pad with 0).
    __half2 fh[8];
    __half  f16h;
    {
        float f[NCH];
#pragma unroll
        for (int ch = 0; ch < NCH; ch++) f[ch] = __ldcs(feats + (size_t)p * NCH + ch);
#pragma unroll
        for (int i = 0; i < 8; i++) fh[i] = __floats2half2_rn(f[2 * i], f[2 * i + 1]);
        f16h = __float2half_rn(f[16]);
    }

    __half* img16 = g16[buf];
    __half* img1  = g1[buf];

    int   iu      = (int)ru;
    bool  u_inner = (ru >= 1.0f) && (ru <= (float)(W_ - 2));  // all 3 dx taps in-bounds

#pragma unroll
    for (int r = 0; r < 3; r++) {
        float pyy = rv + (float)(r - 1);
        if (pyy < 0.0f || pyy >= (float)H_) continue;
        float ddy = pyy - v;
        int   rowbase = (int)pyy * W_ + iu - 1;   // pixel index of dx=-1 tap

        if (u_inner) {
            __half c16[3];
#pragma unroll
            for (int t = 0; t < 3; t++) {
                float ddx = (ru + (float)(t - 1)) - u;
                float e = -0.5f * (ca * ddx * ddx + 2.0f * cb * ddx * ddy + cc * ddy * ddy);
                float w = opac * __expf(e);
                __half2 wh = __float2half2_rn(w);

                __half* bp = img16 + (size_t)(rowbase + t) * 16;
                red_add_v4_h2(bp + 0, h2_bits(__hmul2(wh, fh[0])), h2_bits(__hmul2(wh, fh[1])),
                                      h2_bits(__hmul2(wh, fh[2])), h2_bits(__hmul2(wh, fh[3])));
                red_add_v4_h2(bp + 8, h2_bits(__hmul2(wh, fh[4])), h2_bits(__hmul2(wh, fh[5])),
                                      h2_bits(__hmul2(wh, fh[6])), h2_bits(__hmul2(wh, fh[7])));
                c16[t] = __hmul(__low2half(wh), f16h);
            }
            // merged ch16: 3 contiguous halves -> two 4B-aligned f16x2 REDs (+0 padding)
            const __half hz = __ushort_as_half((unsigned short)0);
            int  e2  = rowbase & ~1;
            bool odd = (rowbase & 1) != 0;
            __half2 h2a = odd ? __halves2half2(hz, c16[0]) : __halves2half2(c16[0], c16[1]);
            __half2 h2b = odd ? __halves2half2(c16[1], c16[2]) : __halves2half2(c16[2], hz);
            red_add_h2(img1 + e2,     h2a);
            red_add_h2(img1 + e2 + 2, h2b);
        } else {
            // border fallback: per-tap guarded (matches reference exactly)
#pragma unroll
            for (int t = 0; t < 3; t++) {
                float pxx = ru + (float)(t - 1);
                if (pxx < 0.0f || pxx >= (float)W_) continue;
                float ddx = pxx - u;
                float e = -0.5f * (ca * ddx * ddx + 2.0f * cb * ddx * ddy + cc * ddy * ddy);
                float w = opac * __expf(e);
                __half2 wh = __float2half2_rn(w);
                int pix = rowbase + t;
                __half* bp = img16 + (size_t)pix * 16;
                red_add_v4_h2(bp + 0, h2_bits(__hmul2(wh, fh[0])), h2_bits(__hmul2(wh, fh[1])),
                                      h2_bits(__hmul2(wh, fh[2])), h2_bits(__hmul2(wh, fh[3])));
                red_add_v4_h2(bp + 8, h2_bits(__hmul2(wh, fh[4])), h2_bits(__hmul2(wh, fh[5])),
                                      h2_bits(__hmul2(wh, fh[6])), h2_bits(__hmul2(wh, fh[7])));
                red_add_h(img1 + pix, __hmul(__low2half(wh), f16h));
            }
        }
    }
}

// Loss: 352 blocks x 256 threads x 8 pixels (MLP-heavy).
__global__ __launch_bounds__(256)
void loss_kernel(int cam, int buf, const int* __restrict__ gt, const float* __restrict__ cw)
{
    float nwl = 0.0f, wv = 0.0f;
    __half* img16 = g16[buf];
    __half* img1  = g1[buf];

#pragma unroll
    for (int j = 0; j < 8; j++) {
        int pix = blockIdx.x * 2048 + j * 256 + threadIdx.x;
        __half* bp = img16 + (size_t)pix * 16;

        uint4 q0 = ((const uint4*)bp)[0];   // halves 0..7
        uint4 q1 = ((const uint4*)bp)[1];   // halves 8..15
        __half h16 = img1[pix];

        float l[NCH];
        {
            float2 t;
            t = __half22float2(*(__half2*)&q0.x); l[0] = t.x;  l[1] = t.y;
            t = __half22float2(*(__half2*)&q0.y); l[2] = t.x;  l[3] = t.y;
            t = __half22float2(*(__half2*)&q0.z); l[4] = t.x;  l[5] = t.y;
            t = __half22float2(*(__half2*)&q0.w); l[6] = t.x;  l[7] = t.y;
            t = __half22float2(*(__half2*)&q1.x); l[8] = t.x;  l[9] = t.y;
            t = __half22float2(*(__half2*)&q1.y); l[10] = t.x; l[11] = t.y;
            t = __half22float2(*(__half2*)&q1.z); l[12] = t.x; l[13] = t.y;
            t = __half22float2(*(__half2*)&q1.w); l[14] = t.x; l[15] = t.y;
            l[16] = __half2float(h16);
        }

        float m = l[0];
#pragma unroll
        for (int ch = 1; ch < NCH; ch++) m = fmaxf(m, l[ch]);
        float s = 0.0f;
#pragma unroll
        for (int ch = 0; ch < NCH; ch++) s += __expf(l[ch] - m);
        float lse = m + __logf(s);

        int g = __ldcs(gt + (size_t)cam * HW + pix);  // in [0,17)
        float lg = (g < 16) ? __half2float(bp[g]) : l[16];
        float w = (g != 0) ? cw[g] : 0.0f;

        nwl += w * (lse - lg);
        wv  += w;

        // restore invariant: zero the image before this buffer's next splat
        uint4 z4 = make_uint4(0u, 0u, 0u, 0u);
        ((uint4*)bp)[0] = z4;
        ((uint4*)bp)[1] = z4;
        img1[pix] = __ushort_as_half((unsigned short)0);
    }

    // block reduction
#pragma unroll
    for (int o = 16; o > 0; o >>= 1) {
        nwl += __shfl_down_sync(0xffffffffu, nwl, o);
        wv  += __shfl_down_sync(0xffffffffu, wv,  o);
    }
    __shared__ float sh[16];
    int lane = threadIdx.x & 31;
    int wid  = threadIdx.x >> 5;
    if (lane == 0) { sh[wid] = nwl; sh[8 + wid] = wv; }
    __syncthreads();
    if (threadIdx.x == 0) {
        float an = 0.0f, ad = 0.0f;
#pragma unroll
        for (int i = 0; i < 8; i++) { an += sh[i]; ad += sh[8 + i]; }
        atomicAdd(&g_num[cam], an);
        atomicAdd(&g_den[cam], ad);
    }
}

__global__ void finalize_kernel(float* out)
{
    if (threadIdx.x == 0 && blockIdx.x == 0) {
        float L = 0.0f;
#pragma unroll
        for (int cam = 0; cam < NCAM; cam++) {
            L += g_num[cam] / fmaxf(g_den[cam], 1e-8f);
            g_num[cam] = 0.0f;   // reset accumulators for next replay
            g_den[cam] = 0.0f;
        }
        out[0] = L / (float)NCAM;
    }
}

// One-time side-streams + fork/join events. Created on the (uncaptured)
// correctness call; captured calls only record/wait — graph-legal fork-join.
static cudaStream_t get_side_stream(int which) {
    static cudaStream_t s[2] = { [] {
        cudaStream_t t;
        cudaStreamCreateWithFlags(&t, cudaStreamNonBlocking);
        return t;
    }(), [] {
        cudaStream_t t;
        cudaStreamCreateWithFlags(&t, cudaStreamNonBlocking);
        return t;
    }() };
    return s[which];
}
static cudaEvent_t get_event(int which) {
    static cudaEvent_t e[3] = { [] {
        cudaEvent_t t;
        cudaEventCreateWithFlags(&t, cudaEventDisableTiming);
        return t;
    }(), [] {
        cudaEvent_t t;
        cudaEventCreateWithFlags(&t, cudaEventDisableTiming);
        return t;
    }(), [] {
        cudaEvent_t t;
        cudaEventCreateWithFlags(&t, cudaEventDisableTiming);
        return t;
    }() };
    return e[which];
}

extern "C" void kernel_launch(void* const* d_in, const int* in_sizes, int n_in,
                              void* d_out, int out_size)
{
    const float* voxel_feats = (const float*)d_in[0];
    const float* density     = (const float*)d_in[1];
    const float* viewmats    = (const float*)d_in[2];
    const float* Ks          = (const float*)d_in[3];
    const int*   gt_sem      = (const int*)d_in[4];
    const float* pc_xyz      = (const float*)d_in[5];
    const float* cls_w       = (const float*)d_in[6];

    cudaStream_t s1 = get_side_stream(0);
    cudaStream_t s2 = get_side_stream(1);
    cudaEvent_t eFork  = get_event(0);
    cudaEvent_t eJoin1 = get_event(1);
    cudaEvent_t eJoin2 = get_event(2);

    // fork: chains 1 and 2 run on side streams, concurrent with chain 0
    cudaEventRecord(eFork, 0);
    cudaStreamWaitEvent(s1, eFork, 0);
    cudaStreamWaitEvent(s2, eFork, 0);

    for (int cam = 0; cam < NCAM; cam++) {
        int chain = cam % NBUF;
        cudaStream_t st = (chain == 0) ? (cudaStream_t)0 : (chain == 1 ? s1 : s2);
        splat_kernel<<<(NPTS + 255) / 256, 256, 0, st>>>(cam, chain, voxel_feats, density,
                                                         viewmats, Ks, pc_xyz);
        loss_kernel<<<HW / 2048, 256, 0, st>>>(cam, chain, gt_sem, cls_w);
    }

    // join: finalize after all three chains complete
    cudaEventRecord(eJoin1, s1);
    cudaEventRecord(eJoin2, s2);
    cudaStreamWaitEvent(0, eJoin1, 0);
    cudaStreamWaitEvent(0, eJoin2, 0);
    finalize_kernel<<<1, 32>>>((float*)d_out);
}